// round 1
// baseline (speedup 1.0000x reference)
#include <cuda_runtime.h>

#define SEQ_LEN 262144
#define HIDDEN 256

// Scratch (device globals — no allocation allowed).
__device__ float4 g_c[SEQ_LEN];   // c_t = B u_t + bA  (w unused)
__device__ float4 g_xs[SEQ_LEN];  // membrane potentials x_t (w unused)

// ---------------------------------------------------------------------------
// Kernel A: c_t = B @ u_t + bA   (parallel, memory bound, ~7MB traffic)
// ---------------------------------------------------------------------------
__global__ void prep_kernel(const float* __restrict__ u,
                            const float* __restrict__ B,
                            const float* __restrict__ bA) {
    int t = blockIdx.x * blockDim.x + threadIdx.x;
    if (t >= SEQ_LEN) return;
    float u0 = u[t];
    float u1 = u[SEQ_LEN + t];
    float u2 = u[2 * SEQ_LEN + t];
    // B is [3,3] row-major
    float c0 = fmaf(B[0], u0, fmaf(B[1], u1, fmaf(B[2], u2, bA[0])));
    float c1 = fmaf(B[3], u0, fmaf(B[4], u1, fmaf(B[5], u2, bA[1])));
    float c2 = fmaf(B[6], u0, fmaf(B[7], u1, fmaf(B[8], u2, bA[2])));
    g_c[t] = make_float4(c0, c1, c2, 0.0f);
}

// ---------------------------------------------------------------------------
// Accurate fast tanh: 1 - 2/(e^{2y}+1) via MUFU ex2/rcp. Abs err ~1e-7.
// Saturates correctly for |y| large (ex2 -> inf/0).
// ---------------------------------------------------------------------------
__device__ __forceinline__ float tanh_fast(float y) {
    float z = y * 2.8853900817779268f;   // 2/ln(2)
    float p;
    asm("ex2.approx.f32 %0, %1;" : "=f"(p) : "f"(z));
    float d = p + 1.0f;
    float r;
    asm("rcp.approx.f32 %0, %1;" : "=f"(r) : "f"(d));
    return fmaf(-2.0f, r, 1.0f);
}

// ---------------------------------------------------------------------------
// Kernel B: the sequential scan. Single thread; everything else is ILP.
// Double-buffered group prefetch of c from L2.
// ---------------------------------------------------------------------------
__global__ void scan_kernel(const float* __restrict__ A,
                            const float* __restrict__ dtp) {
    if (threadIdx.x != 0) return;

    const float a00 = A[0], a01 = A[1], a02 = A[2];
    const float a10 = A[3], a11 = A[4], a12 = A[5];
    const float a20 = A[6], a21 = A[7], a22 = A[8];
    const float dt = dtp[0];

    float x0 = 0.0f, x1 = 0.0f, x2 = 0.0f;

    const int G = 8;
    float4 cbuf[G], cnext[G];

#pragma unroll
    for (int i = 0; i < G; i++) cbuf[i] = g_c[i];

    for (int base = 0; base < SEQ_LEN; base += G) {
        int nb = base + G;
        if (nb < SEQ_LEN) {
#pragma unroll
            for (int i = 0; i < G; i++) cnext[i] = g_c[nb + i];
        }
#pragma unroll
        for (int i = 0; i < G; i++) {
            float4 c = cbuf[i];
            // y_i = A_i. x + c_i  — fma tree, 12cy from x
            float y0 = fmaf(a00, x0, c.x) + fmaf(a02, x2, a01 * x1);
            float y1 = fmaf(a10, x0, c.y) + fmaf(a12, x2, a11 * x1);
            float y2 = fmaf(a20, x0, c.z) + fmaf(a22, x2, a21 * x1);
            float t0 = tanh_fast(y0);
            float t1 = tanh_fast(y1);
            float t2 = tanh_fast(y2);
            x0 = fmaf(dt, t0, x0);
            x1 = fmaf(dt, t1, x1);
            x2 = fmaf(dt, t2, x2);
            g_xs[base + i] = make_float4(x0, x1, x2, 0.0f);
        }
#pragma unroll
        for (int i = 0; i < G; i++) cbuf[i] = cnext[i];
    }
}

// ---------------------------------------------------------------------------
// Kernel C: per-step MLP  out = W2 relu(W1 x + b1) + b2, plus write membrane.
// One thread per timestep; weights packed as float4 in shared memory.
// ---------------------------------------------------------------------------
__global__ void __launch_bounds__(256)
mlp_kernel(const float* __restrict__ W1, const float* __restrict__ b1,
           const float* __restrict__ W2, const float* __restrict__ b2,
           float* __restrict__ out) {
    __shared__ float4 s_w1[HIDDEN];  // {W1[j][0..2], b1[j]}
    __shared__ float4 s_w2[HIDDEN];  // {W2[0][j], W2[1][j], W2[2][j], 0}

    int tid = threadIdx.x;
    {
        int j = tid;  // blockDim.x == HIDDEN == 256
        s_w1[j] = make_float4(W1[3 * j], W1[3 * j + 1], W1[3 * j + 2], b1[j]);
        s_w2[j] = make_float4(W2[j], W2[HIDDEN + j], W2[2 * HIDDEN + j], 0.0f);
    }
    __syncthreads();

    int t = blockIdx.x * blockDim.x + tid;
    float4 x = g_xs[t];
    float o0 = b2[0], o1 = b2[1], o2 = b2[2];

#pragma unroll 8
    for (int j = 0; j < HIDDEN; j++) {
        float4 w = s_w1[j];
        float h = fmaf(w.x, x.x, fmaf(w.y, x.y, fmaf(w.z, x.z, w.w)));
        h = fmaxf(h, 0.0f);
        float4 v = s_w2[j];
        o0 = fmaf(v.x, h, o0);
        o1 = fmaf(v.y, h, o1);
        o2 = fmaf(v.z, h, o2);
    }

    // outputs [3, S] first, then membrane_potentials [3, S]
    out[t] = o0;
    out[SEQ_LEN + t] = o1;
    out[2 * SEQ_LEN + t] = o2;
    float* mem = out + 3 * SEQ_LEN;
    mem[t] = x.x;
    mem[SEQ_LEN + t] = x.y;
    mem[2 * SEQ_LEN + t] = x.z;
}

// ---------------------------------------------------------------------------
extern "C" void kernel_launch(void* const* d_in, const int* in_sizes, int n_in,
                              void* d_out, int out_size) {
    const float* u  = (const float*)d_in[0];
    const float* dt = (const float*)d_in[1];
    const float* A  = (const float*)d_in[2];
    const float* B  = (const float*)d_in[3];
    const float* bA = (const float*)d_in[4];
    const float* W1 = (const float*)d_in[5];
    const float* b1 = (const float*)d_in[6];
    const float* W2 = (const float*)d_in[7];
    const float* b2 = (const float*)d_in[8];
    float* out = (float*)d_out;

    prep_kernel<<<SEQ_LEN / 256, 256>>>(u, B, bA);
    scan_kernel<<<1, 32>>>(A, dt);
    mlp_kernel<<<SEQ_LEN / 256, 256>>>(W1, b1, W2, b2, out);
}

// round 2
// speedup vs baseline: 1.0422x; 1.0422x over previous
#include <cuda_runtime.h>

#define SEQ_LEN 262144
#define HIDDEN 256

// Scratch (device globals — no allocation allowed).
__device__ float4 g_c[SEQ_LEN];   // c_t = B u_t + bA  (w unused)
__device__ float4 g_xs[SEQ_LEN];  // membrane potentials x_t (w unused)

// ---------------------------------------------------------------------------
// Kernel A: c_t = B @ u_t + bA   (parallel, memory bound)
// ---------------------------------------------------------------------------
__global__ void prep_kernel(const float* __restrict__ u,
                            const float* __restrict__ B,
                            const float* __restrict__ bA) {
    int t = blockIdx.x * blockDim.x + threadIdx.x;
    if (t >= SEQ_LEN) return;
    float u0 = u[t];
    float u1 = u[SEQ_LEN + t];
    float u2 = u[2 * SEQ_LEN + t];
    float c0 = fmaf(B[0], u0, fmaf(B[1], u1, fmaf(B[2], u2, bA[0])));
    float c1 = fmaf(B[3], u0, fmaf(B[4], u1, fmaf(B[5], u2, bA[1])));
    float c2 = fmaf(B[6], u0, fmaf(B[7], u1, fmaf(B[8], u2, bA[2])));
    g_c[t] = make_float4(c0, c1, c2, 0.0f);
}

// Single-MUFU tanh (sm_75+). Abs err ~5e-4, but feedback is damped by dt.
__device__ __forceinline__ float tanh_mufu(float y) {
    float r;
    asm("tanh.approx.f32 %0, %1;" : "=f"(r) : "f"(y));
    return r;
}

// ---------------------------------------------------------------------------
// Kernel B: sequential scan. All 32 lanes redundantly compute the identical
// chain; lane i captures step base+i; one coalesced STG.128 per 32 steps.
// Double-buffered broadcast LDG prefetch of c (8-step lookahead).
// ---------------------------------------------------------------------------
__global__ void scan_kernel(const float* __restrict__ A,
                            const float* __restrict__ dtp) {
    const int lane = threadIdx.x & 31;

    const float a00 = A[0], a01 = A[1], a02 = A[2];
    const float a10 = A[3], a11 = A[4], a12 = A[5];
    const float a20 = A[6], a21 = A[7], a22 = A[8];
    const float dt = dtp[0];

    float x0 = 0.0f, x1 = 0.0f, x2 = 0.0f;
    float mx = 0.0f, my = 0.0f, mz = 0.0f;

    float4 cbuf[8], cnext[8];
#pragma unroll
    for (int i = 0; i < 8; i++) cbuf[i] = g_c[i];   // broadcast (same addr all lanes)

    for (int base = 0; base < SEQ_LEN; base += 32) {
#pragma unroll
        for (int ii = 0; ii < 32; ii++) {
            if ((ii & 7) == 0) {
                int nb = base + ii + 8;
                if (nb < SEQ_LEN) {
#pragma unroll
                    for (int j = 0; j < 8; j++) cnext[j] = g_c[nb + j];
                }
            }
            float4 c = cbuf[ii & 7];
            // y_i = A_i . x + c_i  — fma tree, 8cy from x
            float y0 = fmaf(a00, x0, c.x) + fmaf(a02, x2, a01 * x1);
            float y1 = fmaf(a10, x0, c.y) + fmaf(a12, x2, a11 * x1);
            float y2 = fmaf(a20, x0, c.z) + fmaf(a22, x2, a21 * x1);
            float t0 = tanh_mufu(y0);
            float t1 = tanh_mufu(y1);
            float t2 = tanh_mufu(y2);
            x0 = fmaf(dt, t0, x0);
            x1 = fmaf(dt, t1, x1);
            x2 = fmaf(dt, t2, x2);
            if (lane == ii) { mx = x0; my = x1; mz = x2; }   // predicated MOVs, off-chain
            if ((ii & 7) == 7) {
#pragma unroll
                for (int j = 0; j < 8; j++) cbuf[j] = cnext[j];
            }
        }
        // lane i holds state of step base+i — coalesced 512B store
        g_xs[base + lane] = make_float4(mx, my, mz, 0.0f);
    }
}

// ---------------------------------------------------------------------------
// Kernel C: per-step MLP  out = W2 relu(W1 x + b1) + b2, plus write membrane.
// ---------------------------------------------------------------------------
__global__ void __launch_bounds__(256)
mlp_kernel(const float* __restrict__ W1, const float* __restrict__ b1,
           const float* __restrict__ W2, const float* __restrict__ b2,
           float* __restrict__ out) {
    __shared__ float4 s_w1[HIDDEN];  // {W1[j][0..2], b1[j]}
    __shared__ float4 s_w2[HIDDEN];  // {W2[0][j], W2[1][j], W2[2][j], 0}

    int tid = threadIdx.x;
    {
        int j = tid;  // blockDim.x == HIDDEN
        s_w1[j] = make_float4(W1[3 * j], W1[3 * j + 1], W1[3 * j + 2], b1[j]);
        s_w2[j] = make_float4(W2[j], W2[HIDDEN + j], W2[2 * HIDDEN + j], 0.0f);
    }
    __syncthreads();

    int t = blockIdx.x * blockDim.x + tid;
    float4 x = g_xs[t];
    float o0 = b2[0], o1 = b2[1], o2 = b2[2];

#pragma unroll 8
    for (int j = 0; j < HIDDEN; j++) {
        float4 w = s_w1[j];
        float h = fmaf(w.x, x.x, fmaf(w.y, x.y, fmaf(w.z, x.z, w.w)));
        h = fmaxf(h, 0.0f);
        float4 v = s_w2[j];
        o0 = fmaf(v.x, h, o0);
        o1 = fmaf(v.y, h, o1);
        o2 = fmaf(v.z, h, o2);
    }

    out[t] = o0;
    out[SEQ_LEN + t] = o1;
    out[2 * SEQ_LEN + t] = o2;
    float* mem = out + 3 * SEQ_LEN;
    mem[t] = x.x;
    mem[SEQ_LEN + t] = x.y;
    mem[2 * SEQ_LEN + t] = x.z;
}

// ---------------------------------------------------------------------------
extern "C" void kernel_launch(void* const* d_in, const int* in_sizes, int n_in,
                              void* d_out, int out_size) {
    const float* u  = (const float*)d_in[0];
    const float* dt = (const float*)d_in[1];
    const float* A  = (const float*)d_in[2];
    const float* B  = (const float*)d_in[3];
    const float* bA = (const float*)d_in[4];
    const float* W1 = (const float*)d_in[5];
    const float* b1 = (const float*)d_in[6];
    const float* W2 = (const float*)d_in[7];
    const float* b2 = (const float*)d_in[8];
    float* out = (float*)d_out;

    prep_kernel<<<SEQ_LEN / 256, 256>>>(u, B, bA);
    scan_kernel<<<1, 32>>>(A, dt);
    mlp_kernel<<<SEQ_LEN / 256, 256>>>(W1, b1, W2, b2, out);
}

// round 3
// speedup vs baseline: 2.0010x; 1.9199x over previous
#include <cuda_runtime.h>

#define SEQ_LEN 262144
#define HIDDEN 256
#define CHUNK 32

// Scratch (device globals — no allocation allowed).
__device__ float4 g_c[SEQ_LEN];   // c_t = B u_t + bA  (w unused)
__device__ float4 g_xs[SEQ_LEN];  // membrane potentials x_t (w unused)

// ---------------------------------------------------------------------------
// Kernel A: c_t = B @ u_t + bA   (parallel, memory bound)
// ---------------------------------------------------------------------------
__global__ void prep_kernel(const float* __restrict__ u,
                            const float* __restrict__ B,
                            const float* __restrict__ bA) {
    int t = blockIdx.x * blockDim.x + threadIdx.x;
    if (t >= SEQ_LEN) return;
    float u0 = u[t];
    float u1 = u[SEQ_LEN + t];
    float u2 = u[2 * SEQ_LEN + t];
    float c0 = fmaf(B[0], u0, fmaf(B[1], u1, fmaf(B[2], u2, bA[0])));
    float c1 = fmaf(B[3], u0, fmaf(B[4], u1, fmaf(B[5], u2, bA[1])));
    float c2 = fmaf(B[6], u0, fmaf(B[7], u1, fmaf(B[8], u2, bA[2])));
    g_c[t] = make_float4(c0, c1, c2, 0.0f);
}

// Accurate fast tanh: 1 - 2/(e^{2y}+1) via MUFU ex2/rcp. Abs err ~1e-7.
__device__ __forceinline__ float tanh_acc(float y) {
    float z = y * 2.8853900817779268f;   // 2/ln(2)
    float p;
    asm("ex2.approx.f32 %0, %1;" : "=f"(p) : "f"(z));
    float d = p + 1.0f;
    float r;
    asm("rcp.approx.f32 %0, %1;" : "=f"(r) : "f"(d));
    return fmaf(-2.0f, r, 1.0f);
}

// ---------------------------------------------------------------------------
// Kernel B: chunked Taylor scan.
// Per 32-step chunk: (1) warp-parallel tanh + Taylor coeffs at predicted
// arguments yhat_t = c_t + a_chunkstart; (2) serial fma-only recurrence with
// 2nd-order Taylor correction. All lanes redundantly run the serial chain;
// lane ii captures step base+ii; one coalesced STG.128 per chunk.
// ---------------------------------------------------------------------------
__global__ void scan_kernel(const float* __restrict__ A,
                            const float* __restrict__ dtp) {
    __shared__ float4 sT[CHUNK], sD[CHUNK], sE[CHUNK];

    const int lane = threadIdx.x & 31;

    const float a00 = A[0], a01 = A[1], a02 = A[2];
    const float a10 = A[3], a11 = A[4], a12 = A[5];
    const float a20 = A[6], a21 = A[7], a22 = A[8];
    const float dt = dtp[0];

    float x0 = 0.0f, x1 = 0.0f, x2 = 0.0f;   // state
    float w0 = 0.0f, w1 = 0.0f, w2 = 0.0f;   // w = A x (tracked exactly alongside)

    float4 c_cur = g_c[lane];                 // lane's step input for chunk 0

    for (int base = 0; base < SEQ_LEN; base += CHUNK) {
        // chunk-start snapshot of w (linearization center)
        const float s0 = w0, s1 = w1, s2 = w2;

        // ---- parallel phase: lane handles step (base + lane) ----
        {
            float yh0 = c_cur.x + s0;
            float yh1 = c_cur.y + s1;
            float yh2 = c_cur.z + s2;
            float th0 = tanh_acc(yh0);
            float th1 = tanh_acc(yh1);
            float th2 = tanh_acc(yh2);
            float T0 = dt * th0, T1 = dt * th1, T2 = dt * th2;
            float D0 = fmaf(-T0, th0, dt);    // dt*(1 - th^2)
            float D1 = fmaf(-T1, th1, dt);
            float D2 = fmaf(-T2, th2, dt);
            float E0 = -th0 * D0;             // -dt*th*sech^2
            float E1 = -th1 * D1;
            float E2 = -th2 * D2;
            sT[lane] = make_float4(T0, T1, T2, 0.0f);
            sD[lane] = make_float4(D0, D1, D2, 0.0f);
            sE[lane] = make_float4(E0, E1, E2, 0.0f);
        }
        __syncwarp();

        // prefetch next chunk's c (coalesced; consumed next iteration)
        if (base + CHUNK < SEQ_LEN) c_cur = g_c[base + CHUNK + lane];

        // ---- serial phase: 32 steps, fma-only ----
        float mx = 0.0f, my = 0.0f, mz = 0.0f;
#pragma unroll
        for (int ii = 0; ii < CHUNK; ii++) {
            float4 T = sT[ii];
            float4 D = sD[ii];
            float4 E = sE[ii];
            float d0 = w0 - s0, d1 = w1 - s1, d2 = w2 - s2;
            float g0 = fmaf(d0, D.x, T.x);
            float g1 = fmaf(d1, D.y, T.y);
            float g2 = fmaf(d2, D.z, T.z);
            g0 = fmaf(d0 * d0, E.x, g0);      // g = dt*tanh(y) to 2nd order
            g1 = fmaf(d1 * d1, E.y, g1);
            g2 = fmaf(d2 * d2, E.z, g2);
            x0 += g0; x1 += g1; x2 += g2;
            w0 = fmaf(a00, g0, w0); w0 = fmaf(a01, g1, w0); w0 = fmaf(a02, g2, w0);
            w1 = fmaf(a10, g0, w1); w1 = fmaf(a11, g1, w1); w1 = fmaf(a12, g2, w1);
            w2 = fmaf(a20, g0, w2); w2 = fmaf(a21, g1, w2); w2 = fmaf(a22, g2, w2);
            if (lane == ii) { mx = x0; my = x1; mz = x2; }
        }
        __syncwarp();   // protect sT/sD/sE from next chunk's overwrite

        // lane ii holds x after step base+ii — coalesced 512B store
        g_xs[base + lane] = make_float4(mx, my, mz, 0.0f);
    }
}

// ---------------------------------------------------------------------------
// Kernel C: per-step MLP  out = W2 relu(W1 x + b1) + b2, plus write membrane.
// ---------------------------------------------------------------------------
__global__ void __launch_bounds__(256)
mlp_kernel(const float* __restrict__ W1, const float* __restrict__ b1,
           const float* __restrict__ W2, const float* __restrict__ b2,
           float* __restrict__ out) {
    __shared__ float4 s_w1[HIDDEN];  // {W1[j][0..2], b1[j]}
    __shared__ float4 s_w2[HIDDEN];  // {W2[0][j], W2[1][j], W2[2][j], 0}

    int tid = threadIdx.x;
    {
        int j = tid;  // blockDim.x == HIDDEN
        s_w1[j] = make_float4(W1[3 * j], W1[3 * j + 1], W1[3 * j + 2], b1[j]);
        s_w2[j] = make_float4(W2[j], W2[HIDDEN + j], W2[2 * HIDDEN + j], 0.0f);
    }
    __syncthreads();

    int t = blockIdx.x * blockDim.x + tid;
    float4 x = g_xs[t];
    float o0 = b2[0], o1 = b2[1], o2 = b2[2];

#pragma unroll 8
    for (int j = 0; j < HIDDEN; j++) {
        float4 w = s_w1[j];
        float h = fmaf(w.x, x.x, fmaf(w.y, x.y, fmaf(w.z, x.z, w.w)));
        h = fmaxf(h, 0.0f);
        float4 v = s_w2[j];
        o0 = fmaf(v.x, h, o0);
        o1 = fmaf(v.y, h, o1);
        o2 = fmaf(v.z, h, o2);
    }

    out[t] = o0;
    out[SEQ_LEN + t] = o1;
    out[2 * SEQ_LEN + t] = o2;
    float* mem = out + 3 * SEQ_LEN;
    mem[t] = x.x;
    mem[SEQ_LEN + t] = x.y;
    mem[2 * SEQ_LEN + t] = x.z;
}

// ---------------------------------------------------------------------------
extern "C" void kernel_launch(void* const* d_in, const int* in_sizes, int n_in,
                              void* d_out, int out_size) {
    const float* u  = (const float*)d_in[0];
    const float* dt = (const float*)d_in[1];
    const float* A  = (const float*)d_in[2];
    const float* B  = (const float*)d_in[3];
    const float* bA = (const float*)d_in[4];
    const float* W1 = (const float*)d_in[5];
    const float* b1 = (const float*)d_in[6];
    const float* W2 = (const float*)d_in[7];
    const float* b2 = (const float*)d_in[8];
    float* out = (float*)d_out;

    prep_kernel<<<SEQ_LEN / 256, 256>>>(u, B, bA);
    scan_kernel<<<1, 32>>>(A, dt);
    mlp_kernel<<<SEQ_LEN / 256, 256>>>(W1, b1, W2, b2, out);
}

// round 4
// speedup vs baseline: 7.2559x; 3.6262x over previous
#include <cuda_runtime.h>

#define SEQ_LEN 262144
#define HIDDEN 256
#define CHUNK 32
#define NBLK 1024          // SEQ_LEN / 256

// Scratch (device globals — no allocation allowed).
__device__ float4 g_c[SEQ_LEN];     // c_t = B u_t + bA
__device__ float4 g_g[SEQ_LEN];     // per-step increment g_t = dt*tanh(y_t) (approx)
__device__ float4 g_bsum[NBLK];     // per-256-block sums of g
__device__ float4 g_bbase[NBLK];    // exclusive scan of g_bsum

// ---------------------------------------------------------------------------
// Kernel A: c_t = B @ u_t + bA
// ---------------------------------------------------------------------------
__global__ void prep_kernel(const float* __restrict__ u,
                            const float* __restrict__ B,
                            const float* __restrict__ bA) {
    int t = blockIdx.x * blockDim.x + threadIdx.x;
    if (t >= SEQ_LEN) return;
    float u0 = u[t];
    float u1 = u[SEQ_LEN + t];
    float u2 = u[2 * SEQ_LEN + t];
    float c0 = fmaf(B[0], u0, fmaf(B[1], u1, fmaf(B[2], u2, bA[0])));
    float c1 = fmaf(B[3], u0, fmaf(B[4], u1, fmaf(B[5], u2, bA[1])));
    float c2 = fmaf(B[6], u0, fmaf(B[7], u1, fmaf(B[8], u2, bA[2])));
    g_c[t] = make_float4(c0, c1, c2, 0.0f);
}

// Accurate fast tanh: 1 - 2/(e^{2y}+1) via MUFU ex2/rcp. Abs err ~1e-7.
__device__ __forceinline__ float tanh_acc(float y) {
    float z = y * 2.8853900817779268f;   // 2/ln(2)
    float p;
    asm("ex2.approx.f32 %0, %1;" : "=f"(p) : "f"(z));
    float d = p + 1.0f;
    float r;
    asm("rcp.approx.f32 %0, %1;" : "=f"(r) : "f"(d));
    return fmaf(-2.0f, r, 1.0f);
}

// Kogge-Stone inclusive add-scan of 3 components across the warp.
__device__ __forceinline__ void wscan3(float& a, float& b, float& c, int lane) {
#pragma unroll
    for (int off = 1; off < 32; off <<= 1) {
        float ta = __shfl_up_sync(0xffffffffu, a, off);
        float tb = __shfl_up_sync(0xffffffffu, b, off);
        float tc = __shfl_up_sync(0xffffffffu, c, off);
        if (lane >= off) { a += ta; b += tb; c += tc; }
    }
}

// ---------------------------------------------------------------------------
// Kernel B: warp-affine-scan over 32-step chunks.
// Lane t of each chunk computes Taylor coeffs at yhat = c_t + s, then two
// warp scans deliver delta_t = (w_t - s) to first order; g_t emitted per lane.
// Only the 3-float w state is chunk-serial.
// ---------------------------------------------------------------------------
__global__ void scan_kernel(const float* __restrict__ A,
                            const float* __restrict__ dtp) {
    const int lane = threadIdx.x & 31;

    const float a00 = A[0], a01 = A[1], a02 = A[2];
    const float a10 = A[3], a11 = A[4], a12 = A[5];
    const float a20 = A[6], a21 = A[7], a22 = A[8];
    const float dt = dtp[0];

    float s0 = 0.0f, s1 = 0.0f, s2 = 0.0f;      // w = A x at chunk start

    float4 c_cur = g_c[lane];

    for (int base = 0; base < SEQ_LEN; base += CHUNK) {
        float4 c = c_cur;
        if (base + CHUNK < SEQ_LEN) c_cur = g_c[base + CHUNK + lane];

        // ---- per-lane Taylor coefficients at predicted argument ----
        float th0 = tanh_acc(c.x + s0);
        float th1 = tanh_acc(c.y + s1);
        float th2 = tanh_acc(c.z + s2);
        float T0 = dt * th0, T1 = dt * th1, T2 = dt * th2;
        float D0 = fmaf(-T0, th0, dt);           // dt*sech^2
        float D1 = fmaf(-T1, th1, dt);
        float D2 = fmaf(-T2, th2, dt);
        float E0 = -th0 * D0;                    // -dt*th*sech^2
        float E1 = -th1 * D1;
        float E2 = -th2 * D2;

        // v = A T
        float v0 = fmaf(a00, T0, fmaf(a01, T1, a02 * T2));
        float v1 = fmaf(a10, T0, fmaf(a11, T1, a12 * T2));
        float v2 = fmaf(a20, T0, fmaf(a21, T1, a22 * T2));

        // ---- scan 1: V (zeroth-order delta) ----
        float Iv0 = v0, Iv1 = v1, Iv2 = v2;
        wscan3(Iv0, Iv1, Iv2, lane);
        float V0 = Iv0 - v0, V1 = Iv1 - v1, V2 = Iv2 - v2;   // exclusive

        // ---- first-order correction source: r = A (D.V + E.V^2) ----
        float q0 = V0 * fmaf(E0, V0, D0);
        float q1 = V1 * fmaf(E1, V1, D1);
        float q2 = V2 * fmaf(E2, V2, D2);
        float r0 = fmaf(a00, q0, fmaf(a01, q1, a02 * q2));
        float r1 = fmaf(a10, q0, fmaf(a11, q1, a12 * q2));
        float r2 = fmaf(a20, q0, fmaf(a21, q1, a22 * q2));

        // ---- scan 2: R ----
        float Ir0 = r0, Ir1 = r1, Ir2 = r2;
        wscan3(Ir0, Ir1, Ir2, lane);
        float R0 = Ir0 - r0, R1 = Ir1 - r1, R2 = Ir2 - r2;   // exclusive

        // ---- delta and per-step increment ----
        float d0 = V0 + R0, d1 = V1 + R1, d2 = V2 + R2;
        float g0 = fmaf(d0, fmaf(E0, d0, D0), T0);
        float g1 = fmaf(d1, fmaf(E1, d1, D1), T1);
        float g2 = fmaf(d2, fmaf(E2, d2, D2), T2);

        g_g[base + lane] = make_float4(g0, g1, g2, 0.0f);

        // ---- advance w to chunk end (lane 31 inclusive totals) ----
        float t0 = Iv0 + Ir0, t1 = Iv1 + Ir1, t2 = Iv2 + Ir2;
        s0 += __shfl_sync(0xffffffffu, t0, 31);
        s1 += __shfl_sync(0xffffffffu, t1, 31);
        s2 += __shfl_sync(0xffffffffu, t2, 31);
    }
}

// ---------------------------------------------------------------------------
// Kernel S1: per-256-step block sums of g.
// ---------------------------------------------------------------------------
__global__ void __launch_bounds__(256)
sum_kernel() {
    __shared__ float4 wsum[8];
    int tid = threadIdx.x;
    int lane = tid & 31, wid = tid >> 5;
    float4 g = g_g[blockIdx.x * 256 + tid];
    float a = g.x, b = g.y, c = g.z;
#pragma unroll
    for (int off = 16; off > 0; off >>= 1) {
        a += __shfl_down_sync(0xffffffffu, a, off);
        b += __shfl_down_sync(0xffffffffu, b, off);
        c += __shfl_down_sync(0xffffffffu, c, off);
    }
    if (lane == 0) wsum[wid] = make_float4(a, b, c, 0.0f);
    __syncthreads();
    if (tid == 0) {
        float x = 0.f, y = 0.f, z = 0.f;
#pragma unroll
        for (int k = 0; k < 8; k++) { x += wsum[k].x; y += wsum[k].y; z += wsum[k].z; }
        g_bsum[blockIdx.x] = make_float4(x, y, z, 0.0f);
    }
}

// ---------------------------------------------------------------------------
// Kernel S2: exclusive scan of the 1024 block sums (single block).
// ---------------------------------------------------------------------------
__global__ void __launch_bounds__(1024)
bscan_kernel() {
    __shared__ float4 buf[NBLK];
    int t = threadIdx.x;
    buf[t] = g_bsum[t];
    __syncthreads();
#pragma unroll
    for (int off = 1; off < NBLK; off <<= 1) {
        float4 add = make_float4(0.f, 0.f, 0.f, 0.f);
        if (t >= off) add = buf[t - off];
        __syncthreads();
        if (t >= off) {
            buf[t].x += add.x; buf[t].y += add.y; buf[t].z += add.z;
        }
        __syncthreads();
    }
    float4 ex = (t == 0) ? make_float4(0.f, 0.f, 0.f, 0.f) : buf[t - 1];
    g_bbase[t] = ex;
}

// ---------------------------------------------------------------------------
// Kernel C: reconstruct x (block prefix of g + base) then MLP + outputs.
// ---------------------------------------------------------------------------
__global__ void __launch_bounds__(256)
mlp_kernel(const float* __restrict__ W1, const float* __restrict__ b1,
           const float* __restrict__ W2, const float* __restrict__ b2,
           float* __restrict__ out) {
    __shared__ float4 s_w1[HIDDEN];
    __shared__ float4 s_w2[HIDDEN];
    __shared__ float4 wtot[8];

    int tid = threadIdx.x;
    int lane = tid & 31, wid = tid >> 5;
    {
        int j = tid;
        s_w1[j] = make_float4(W1[3 * j], W1[3 * j + 1], W1[3 * j + 2], b1[j]);
        s_w2[j] = make_float4(W2[j], W2[HIDDEN + j], W2[2 * HIDDEN + j], 0.0f);
    }

    int t = blockIdx.x * 256 + tid;
    float4 g = g_g[t];
    float x0 = g.x, x1 = g.y, x2 = g.z;
    wscan3(x0, x1, x2, lane);                    // warp-inclusive
    if (lane == 31) wtot[wid] = make_float4(x0, x1, x2, 0.0f);
    __syncthreads();
    float4 base = g_bbase[blockIdx.x];
    float b0 = base.x, b1v = base.y, b2v = base.z;
    for (int k = 0; k < wid; k++) {
        b0 += wtot[k].x; b1v += wtot[k].y; b2v += wtot[k].z;
    }
    x0 += b0; x1 += b1v; x2 += b2v;              // x after step t

    float o0 = b2[0], o1 = b2[1], o2 = b2[2];
#pragma unroll 8
    for (int j = 0; j < HIDDEN; j++) {
        float4 w = s_w1[j];
        float h = fmaf(w.x, x0, fmaf(w.y, x1, fmaf(w.z, x2, w.w)));
        h = fmaxf(h, 0.0f);
        float4 v = s_w2[j];
        o0 = fmaf(v.x, h, o0);
        o1 = fmaf(v.y, h, o1);
        o2 = fmaf(v.z, h, o2);
    }

    out[t] = o0;
    out[SEQ_LEN + t] = o1;
    out[2 * SEQ_LEN + t] = o2;
    float* mem = out + 3 * SEQ_LEN;
    mem[t] = x0;
    mem[SEQ_LEN + t] = x1;
    mem[2 * SEQ_LEN + t] = x2;
}

// ---------------------------------------------------------------------------
extern "C" void kernel_launch(void* const* d_in, const int* in_sizes, int n_in,
                              void* d_out, int out_size) {
    const float* u  = (const float*)d_in[0];
    const float* dt = (const float*)d_in[1];
    const float* A  = (const float*)d_in[2];
    const float* B  = (const float*)d_in[3];
    const float* bA = (const float*)d_in[4];
    const float* W1 = (const float*)d_in[5];
    const float* b1 = (const float*)d_in[6];
    const float* W2 = (const float*)d_in[7];
    const float* b2 = (const float*)d_in[8];
    float* out = (float*)d_out;

    prep_kernel<<<SEQ_LEN / 256, 256>>>(u, B, bA);
    scan_kernel<<<1, 32>>>(A, dt);
    sum_kernel<<<NBLK, 256>>>();
    bscan_kernel<<<1, NBLK>>>();
    mlp_kernel<<<NBLK, 256>>>(W1, b1, W2, b2, out);
}

// round 5
// speedup vs baseline: 15.4149x; 2.1245x over previous
#include <cuda_runtime.h>

#define SEQ_LEN 262144
#define HIDDEN 256
#define CHUNK 128
#define NWARP 4
#define NBLK 1024          // SEQ_LEN / 256

// Scratch (device globals — no allocation allowed).
__device__ float4 g_c[SEQ_LEN];     // c_t = B u_t + bA
__device__ float4 g_g[SEQ_LEN];     // per-step increment g_t = dt*tanh(y_t) (approx)
__device__ float4 g_bsum[NBLK];     // per-256-block sums of g
__device__ float4 g_bbase[NBLK];    // exclusive scan of g_bsum

// ---------------------------------------------------------------------------
// Kernel A: c_t = B @ u_t + bA
// ---------------------------------------------------------------------------
__global__ void prep_kernel(const float* __restrict__ u,
                            const float* __restrict__ B,
                            const float* __restrict__ bA) {
    int t = blockIdx.x * blockDim.x + threadIdx.x;
    if (t >= SEQ_LEN) return;
    float u0 = u[t];
    float u1 = u[SEQ_LEN + t];
    float u2 = u[2 * SEQ_LEN + t];
    float c0 = fmaf(B[0], u0, fmaf(B[1], u1, fmaf(B[2], u2, bA[0])));
    float c1 = fmaf(B[3], u0, fmaf(B[4], u1, fmaf(B[5], u2, bA[1])));
    float c2 = fmaf(B[6], u0, fmaf(B[7], u1, fmaf(B[8], u2, bA[2])));
    g_c[t] = make_float4(c0, c1, c2, 0.0f);
}

// Accurate fast tanh: 1 - 2/(e^{2y}+1) via MUFU ex2/rcp. Abs err ~1e-7.
__device__ __forceinline__ float tanh_acc(float y) {
    float z = y * 2.8853900817779268f;   // 2/ln(2)
    float p;
    asm("ex2.approx.f32 %0, %1;" : "=f"(p) : "f"(z));
    float d = p + 1.0f;
    float r;
    asm("rcp.approx.f32 %0, %1;" : "=f"(r) : "f"(d));
    return fmaf(-2.0f, r, 1.0f);
}

// Kogge-Stone inclusive add-scan of 3 components across one warp.
__device__ __forceinline__ void wscan3(float& a, float& b, float& c, int lane) {
#pragma unroll
    for (int off = 1; off < 32; off <<= 1) {
        float ta = __shfl_up_sync(0xffffffffu, a, off);
        float tb = __shfl_up_sync(0xffffffffu, b, off);
        float tc = __shfl_up_sync(0xffffffffu, c, off);
        if (lane >= off) { a += ta; b += tb; c += tc; }
    }
}

// ---------------------------------------------------------------------------
// Kernel B: block-affine-scan over 128-step chunks (4 warps).
// Three Neumann-order scans (V, R1, R2) across 128 lanes; chunk-serial state
// is just w (3 floats). Cross-warp combine via double-buffered smem totals.
// ---------------------------------------------------------------------------
__global__ void __launch_bounds__(CHUNK)
scan_kernel(const float* __restrict__ A,
            const float* __restrict__ dtp) {
    // double-buffered per-warp totals for the 3 scans
    __shared__ float4 sV[2][NWARP], sR1[2][NWARP], sR2[2][NWARP];

    const int tid = threadIdx.x;
    const int lane = tid & 31;
    const int wid = tid >> 5;

    const float a00 = A[0], a01 = A[1], a02 = A[2];
    const float a10 = A[3], a11 = A[4], a12 = A[5];
    const float a20 = A[6], a21 = A[7], a22 = A[8];
    const float dt = dtp[0];

    float s0 = 0.0f, s1 = 0.0f, s2 = 0.0f;      // w = A x at chunk start

    float4 c_cur = g_c[tid];
    int p = 0;

    for (int base = 0; base < SEQ_LEN; base += CHUNK) {
        float4 c = c_cur;
        if (base + CHUNK < SEQ_LEN) c_cur = g_c[base + CHUNK + tid];

        // ---- per-lane Taylor coefficients at predicted argument ----
        float th0 = tanh_acc(c.x + s0);
        float th1 = tanh_acc(c.y + s1);
        float th2 = tanh_acc(c.z + s2);
        float T0 = dt * th0, T1 = dt * th1, T2 = dt * th2;
        float D0 = fmaf(-T0, th0, dt);           // dt*sech^2
        float D1 = fmaf(-T1, th1, dt);
        float D2 = fmaf(-T2, th2, dt);
        float E0 = -th0 * D0;                    // -dt*th*sech^2
        float E1 = -th1 * D1;
        float E2 = -th2 * D2;

        // v = A T
        float v0 = fmaf(a00, T0, fmaf(a01, T1, a02 * T2));
        float v1 = fmaf(a10, T0, fmaf(a11, T1, a12 * T2));
        float v2 = fmaf(a20, T0, fmaf(a21, T1, a22 * T2));

        // ---- scan 1: V (zeroth order) ----
        float Iv0 = v0, Iv1 = v1, Iv2 = v2;
        wscan3(Iv0, Iv1, Iv2, lane);
        if (lane == 31) sV[p][wid] = make_float4(Iv0, Iv1, Iv2, 0.0f);
        __syncthreads();
        float pv0 = 0.f, pv1 = 0.f, pv2 = 0.f;        // prefix from earlier warps
        float tv0 = 0.f, tv1 = 0.f, tv2 = 0.f;        // chunk total
#pragma unroll
        for (int k = 0; k < NWARP; k++) {
            float4 w = sV[p][k];
            tv0 += w.x; tv1 += w.y; tv2 += w.z;
            if (k < wid) { pv0 += w.x; pv1 += w.y; pv2 += w.z; }
        }
        float V0 = Iv0 - v0 + pv0;                    // global exclusive
        float V1 = Iv1 - v1 + pv1;
        float V2 = Iv2 - v2 + pv2;

        // ---- correction 1: r1 = A (D.V + E.V^2) ----
        float q0 = V0 * fmaf(E0, V0, D0);
        float q1 = V1 * fmaf(E1, V1, D1);
        float q2 = V2 * fmaf(E2, V2, D2);
        float r0 = fmaf(a00, q0, fmaf(a01, q1, a02 * q2));
        float r1 = fmaf(a10, q0, fmaf(a11, q1, a12 * q2));
        float r2 = fmaf(a20, q0, fmaf(a21, q1, a22 * q2));

        float Ir0 = r0, Ir1 = r1, Ir2 = r2;
        wscan3(Ir0, Ir1, Ir2, lane);
        if (lane == 31) sR1[p][wid] = make_float4(Ir0, Ir1, Ir2, 0.0f);
        __syncthreads();
        float pr0 = 0.f, pr1 = 0.f, pr2 = 0.f;
        float tr0 = 0.f, tr1 = 0.f, tr2 = 0.f;
#pragma unroll
        for (int k = 0; k < NWARP; k++) {
            float4 w = sR1[p][k];
            tr0 += w.x; tr1 += w.y; tr2 += w.z;
            if (k < wid) { pr0 += w.x; pr1 += w.y; pr2 += w.z; }
        }
        float R10 = Ir0 - r0 + pr0;
        float R11 = Ir1 - r1 + pr1;
        float R12 = Ir2 - r2 + pr2;

        // ---- correction 2: r2 = A (D.R1 + 2E.V.R1) ----
        float u0c = R10 * fmaf(2.0f * E0, V0, D0);
        float u1c = R11 * fmaf(2.0f * E1, V1, D1);
        float u2c = R12 * fmaf(2.0f * E2, V2, D2);
        float z0 = fmaf(a00, u0c, fmaf(a01, u1c, a02 * u2c));
        float z1 = fmaf(a10, u0c, fmaf(a11, u1c, a12 * u2c));
        float z2 = fmaf(a20, u0c, fmaf(a21, u1c, a22 * u2c));

        float Iz0 = z0, Iz1 = z1, Iz2 = z2;
        wscan3(Iz0, Iz1, Iz2, lane);
        if (lane == 31) sR2[p][wid] = make_float4(Iz0, Iz1, Iz2, 0.0f);
        __syncthreads();
        float pz0 = 0.f, pz1 = 0.f, pz2 = 0.f;
        float tz0 = 0.f, tz1 = 0.f, tz2 = 0.f;
#pragma unroll
        for (int k = 0; k < NWARP; k++) {
            float4 w = sR2[p][k];
            tz0 += w.x; tz1 += w.y; tz2 += w.z;
            if (k < wid) { pz0 += w.x; pz1 += w.y; pz2 += w.z; }
        }
        float R20 = Iz0 - z0 + pz0;
        float R21 = Iz1 - z1 + pz1;
        float R22 = Iz2 - z2 + pz2;

        // ---- delta and per-step increment ----
        float d0 = V0 + R10 + R20;
        float d1 = V1 + R11 + R21;
        float d2 = V2 + R12 + R22;
        float g0 = fmaf(d0, fmaf(E0, d0, D0), T0);
        float g1 = fmaf(d1, fmaf(E1, d1, D1), T1);
        float g2 = fmaf(d2, fmaf(E2, d2, D2), T2);

        g_g[base + tid] = make_float4(g0, g1, g2, 0.0f);

        // ---- advance w by full-chunk totals ----
        s0 += tv0 + tr0 + tz0;
        s1 += tv1 + tr1 + tz1;
        s2 += tv2 + tr2 + tz2;

        p ^= 1;   // double-buffer totals; WAR separated by >=2 barriers
    }
}

// ---------------------------------------------------------------------------
// Kernel S1: per-256-step block sums of g.
// ---------------------------------------------------------------------------
__global__ void __launch_bounds__(256)
sum_kernel() {
    __shared__ float4 wsum[8];
    int tid = threadIdx.x;
    int lane = tid & 31, wid = tid >> 5;
    float4 g = g_g[blockIdx.x * 256 + tid];
    float a = g.x, b = g.y, c = g.z;
#pragma unroll
    for (int off = 16; off > 0; off >>= 1) {
        a += __shfl_down_sync(0xffffffffu, a, off);
        b += __shfl_down_sync(0xffffffffu, b, off);
        c += __shfl_down_sync(0xffffffffu, c, off);
    }
    if (lane == 0) wsum[wid] = make_float4(a, b, c, 0.0f);
    __syncthreads();
    if (tid == 0) {
        float x = 0.f, y = 0.f, z = 0.f;
#pragma unroll
        for (int k = 0; k < 8; k++) { x += wsum[k].x; y += wsum[k].y; z += wsum[k].z; }
        g_bsum[blockIdx.x] = make_float4(x, y, z, 0.0f);
    }
}

// ---------------------------------------------------------------------------
// Kernel S2: exclusive scan of the 1024 block sums (single block).
// ---------------------------------------------------------------------------
__global__ void __launch_bounds__(1024)
bscan_kernel() {
    __shared__ float4 buf[NBLK];
    int t = threadIdx.x;
    buf[t] = g_bsum[t];
    __syncthreads();
#pragma unroll
    for (int off = 1; off < NBLK; off <<= 1) {
        float4 add = make_float4(0.f, 0.f, 0.f, 0.f);
        if (t >= off) add = buf[t - off];
        __syncthreads();
        if (t >= off) {
            buf[t].x += add.x; buf[t].y += add.y; buf[t].z += add.z;
        }
        __syncthreads();
    }
    float4 ex = (t == 0) ? make_float4(0.f, 0.f, 0.f, 0.f) : buf[t - 1];
    g_bbase[t] = ex;
}

// ---------------------------------------------------------------------------
// Kernel C: reconstruct x (block prefix of g + base) then MLP + outputs.
// ---------------------------------------------------------------------------
__global__ void __launch_bounds__(256)
mlp_kernel(const float* __restrict__ W1, const float* __restrict__ b1,
           const float* __restrict__ W2, const float* __restrict__ b2,
           float* __restrict__ out) {
    __shared__ float4 s_w1[HIDDEN];
    __shared__ float4 s_w2[HIDDEN];
    __shared__ float4 wtot[8];

    int tid = threadIdx.x;
    int lane = tid & 31, wid = tid >> 5;
    {
        int j = tid;
        s_w1[j] = make_float4(W1[3 * j], W1[3 * j + 1], W1[3 * j + 2], b1[j]);
        s_w2[j] = make_float4(W2[j], W2[HIDDEN + j], W2[2 * HIDDEN + j], 0.0f);
    }

    int t = blockIdx.x * 256 + tid;
    float4 g = g_g[t];
    float x0 = g.x, x1 = g.y, x2 = g.z;
    wscan3(x0, x1, x2, lane);                    // warp-inclusive
    if (lane == 31) wtot[wid] = make_float4(x0, x1, x2, 0.0f);
    __syncthreads();
    float4 base = g_bbase[blockIdx.x];
    float b0 = base.x, b1v = base.y, b2v = base.z;
    for (int k = 0; k < wid; k++) {
        b0 += wtot[k].x; b1v += wtot[k].y; b2v += wtot[k].z;
    }
    x0 += b0; x1 += b1v; x2 += b2v;              // x after step t

    float o0 = b2[0], o1 = b2[1], o2 = b2[2];
#pragma unroll 8
    for (int j = 0; j < HIDDEN; j++) {
        float4 w = s_w1[j];
        float h = fmaf(w.x, x0, fmaf(w.y, x1, fmaf(w.z, x2, w.w)));
        h = fmaxf(h, 0.0f);
        float4 v = s_w2[j];
        o0 = fmaf(v.x, h, o0);
        o1 = fmaf(v.y, h, o1);
        o2 = fmaf(v.z, h, o2);
    }

    out[t] = o0;
    out[SEQ_LEN + t] = o1;
    out[2 * SEQ_LEN + t] = o2;
    float* mem = out + 3 * SEQ_LEN;
    mem[t] = x0;
    mem[SEQ_LEN + t] = x1;
    mem[2 * SEQ_LEN + t] = x2;
}

// ---------------------------------------------------------------------------
extern "C" void kernel_launch(void* const* d_in, const int* in_sizes, int n_in,
                              void* d_out, int out_size) {
    const float* u  = (const float*)d_in[0];
    const float* dt = (const float*)d_in[1];
    const float* A  = (const float*)d_in[2];
    const float* B  = (const float*)d_in[3];
    const float* bA = (const float*)d_in[4];
    const float* W1 = (const float*)d_in[5];
    const float* b1 = (const float*)d_in[6];
    const float* W2 = (const float*)d_in[7];
    const float* b2 = (const float*)d_in[8];
    float* out = (float*)d_out;

    prep_kernel<<<SEQ_LEN / 256, 256>>>(u, B, bA);
    scan_kernel<<<1, CHUNK>>>(A, dt);
    sum_kernel<<<NBLK, 256>>>();
    bscan_kernel<<<1, NBLK>>>();
    mlp_kernel<<<NBLK, 256>>>(W1, b1, W2, b2, out);
}